// round 1
// baseline (speedup 1.0000x reference)
#include <cuda_runtime.h>
#include <math.h>

// ---------------- problem constants (fixed shapes) ----------------
#define BB   128
#define DD   512
#define SS   30
#define HW   196
#define TT   12
#define NH   13          // TT+1 history slots
#define BDSZ (BB*DD)     // 65536

// ---------------- device scratch (no allocation allowed) ----------------
__device__ float g_KBp[(size_t)BB*HW*DD];   // (B, HW, D)  51.4 MB
__device__ float g_chist[(size_t)NH*BDSZ];
__device__ float g_mhist[(size_t)NH*BDSZ];
__device__ float g_qi[BDSZ];
__device__ float g_cq[BDSZ];
__device__ float g_v[BDSZ];
__device__ float g_mp[BDSZ];
__device__ float g_U[(size_t)BB*2*DD];      // cols 0..511 hold y = mp*u1 after epilogue
__device__ float g_z[BDSZ];
__device__ float g_mnew[BDSZ];
__device__ float g_m1[BDSZ];
__device__ float g_msa[BDSZ];
__device__ float g_g[BDSZ];

// ---------------- transpose KB (B,D,HW) -> KBp (B,HW,D) ----------------
__global__ void transpose_kb_k(const float* __restrict__ KB, float* __restrict__ KBp)
{
    __shared__ float tile[32][33];
    int b = blockIdx.z;
    int hw0 = blockIdx.x * 32, d0 = blockIdx.y * 32;
    int tx = threadIdx.x, ty = threadIdx.y;        // 32 x 8
    const float* src = KB + (size_t)b * DD * HW;
#pragma unroll
    for (int j = 0; j < 4; j++) {
        int d = d0 + ty + j * 8;
        int hw = hw0 + tx;
        if (hw < HW) tile[ty + j * 8][tx] = src[(size_t)d * HW + hw];
    }
    __syncthreads();
    float* dst = KBp + (size_t)b * HW * DD;
#pragma unroll
    for (int j = 0; j < 4; j++) {
        int hw = hw0 + ty + j * 8;
        if (hw < HW) dst[(size_t)hw * DD + d0 + tx] = tile[tx][ty + j * 8];
    }
}

// ---------------- generic skinny GEMM: out(128 x N) = [A0|A1](128 x K) * W ----------------
// WNT=false: W is (K,N) row-major (X @ W).  WNT=true: W is (N,K) row-major (X @ W^T).
// EPI: 0 = +bias(optional); 1 = sigmoid(+bias); 2 = (c<ldp1)? acc*P1[r,c] : acc;
//      3 = acc + P1[r*ldp1+c]; 4 = gate: m2=acc+bias; out = g*mprev + (1-g)*m2
template<bool WNT, int EPI>
__global__ void __launch_bounds__(256)
gemm_k(const float* __restrict__ A0, const float* __restrict__ A1,
       int lda0, int lda1, int K0, int K,
       const float* __restrict__ W,
       const float* __restrict__ bias,
       float* __restrict__ out, int ldo, int N,
       const float* __restrict__ P1, int ldp1,
       const float* __restrict__ P2)
{
    __shared__ float As[64][33];   // [row][kk]
    __shared__ float Ws[32][9];    // [kk][n]
    int tid = threadIdx.x;
    int r0 = blockIdx.y * 64, n0 = blockIdx.x * 8;
    int r = tid & 63, cg = tid >> 6;      // cg 0..3
    int cl = cg * 2;
    float acc0 = 0.f, acc1 = 0.f;

    for (int k0 = 0; k0 < K; k0 += 32) {
        // load A tile: 64 rows x 32 k
        {
            int kk = tid & 31, row = tid >> 5;  // row 0..7
#pragma unroll
            for (int j = 0; j < 8; j++) {
                int rr = row + j * 8;
                int gk = k0 + kk;
                float val = (gk < K0) ? A0[(size_t)(r0 + rr) * lda0 + gk]
                                      : A1[(size_t)(r0 + rr) * lda1 + (gk - K0)];
                As[rr][kk] = val;
            }
        }
        // load W tile: 32 k x 8 n
        if (tid < 256) {
            if (WNT) {
                int kk = tid & 31, n = tid >> 5;
                Ws[kk][n] = W[(size_t)(n0 + n) * K + (k0 + kk)];
            } else {
                int n = tid & 7, kk = tid >> 3;
                Ws[kk][n] = W[(size_t)(k0 + kk) * N + (n0 + n)];
            }
        }
        __syncthreads();
#pragma unroll
        for (int kk = 0; kk < 32; kk++) {
            float a = As[r][kk];
            acc0 += a * Ws[kk][cl];
            acc1 += a * Ws[kk][cl + 1];
        }
        __syncthreads();
    }

    int rg = r0 + r;
#pragma unroll
    for (int q = 0; q < 2; q++) {
        float acc = (q == 0) ? acc0 : acc1;
        int c = n0 + cl + q;
        if (EPI == 0) {
            if (bias) acc += bias[c];
            out[(size_t)rg * ldo + c] = acc;
        } else if (EPI == 1) {
            acc += bias[c];
            out[(size_t)rg * ldo + c] = 1.f / (1.f + expf(-acc));
        } else if (EPI == 2) {
            if (c < ldp1) acc *= P1[(size_t)rg * ldp1 + c];
            out[(size_t)rg * ldo + c] = acc;
        } else if (EPI == 3) {
            acc += P1[(size_t)rg * ldp1 + c];
            out[(size_t)rg * ldo + c] = acc;
        } else { // EPI == 4 : gate
            float m2 = acc + bias[c];
            float gg = P1[(size_t)rg * ldp1 + c];
            float mprev = P2[(size_t)rg * ldp1 + c];
            out[(size_t)rg * ldo + c] = gg * mprev + (1.f - gg) * m2;
        }
    }
}

// ---------------- control unit attention (one block per batch, 128 threads) ----------------
__global__ void __launch_bounds__(128)
control_attn_k(const float* __restrict__ cq, const float* __restrict__ cws,
               const float* __restrict__ wca, const float* __restrict__ wra,
               float* __restrict__ ci_out, float* __restrict__ v)
{
    int b = blockIdx.x, tid = threadIdx.x;
    float acc[SS];
#pragma unroll
    for (int s = 0; s < SS; s++) acc[s] = 0.f;
#pragma unroll
    for (int i = 0; i < 4; i++) {
        int d = tid + i * 128;
        float a = cq[(size_t)b * DD + d] * wca[d];
        const float* row = cws + ((size_t)b * DD + d) * SS;
#pragma unroll
        for (int s = 0; s < SS; s++) acc[s] += a * row[s];
    }
    __shared__ float wred[4][SS];
    int lane = tid & 31, warp = tid >> 5;
#pragma unroll
    for (int s = 0; s < SS; s++) {
        float x = acc[s];
        for (int off = 16; off; off >>= 1) x += __shfl_down_sync(~0u, x, off);
        if (lane == 0) wred[warp][s] = x;
    }
    __syncthreads();
    __shared__ float cattn[SS];
    if (warp == 0) {
        float val = (lane < SS) ? (wred[0][lane] + wred[1][lane] + wred[2][lane] + wred[3][lane]) : -1e30f;
        float mx = val;
        for (int off = 16; off; off >>= 1) mx = fmaxf(mx, __shfl_xor_sync(~0u, mx, off));
        float e = (lane < SS) ? expf(val - mx) : 0.f;
        float tot = e;
        for (int off = 16; off; off >>= 1) tot += __shfl_xor_sync(~0u, tot, off);
        if (lane < SS) cattn[lane] = e / tot;
    }
    __syncthreads();
#pragma unroll
    for (int i = 0; i < 4; i++) {
        int d = tid + i * 128;
        const float* row = cws + ((size_t)b * DD + d) * SS;
        float ci = 0.f;
#pragma unroll
        for (int s = 0; s < SS; s++) ci += cattn[s] * row[s];
        ci_out[(size_t)b * DD + d] = ci;
        v[(size_t)b * DD + d] = ci * wra[d];
    }
}

// ---------------- read unit attention (one block per batch, 512 threads) ----------------
__global__ void __launch_bounds__(512)
read_attn_k(const float* __restrict__ KBp, const float* __restrict__ z,
            float* __restrict__ mnew)
{
    int b = blockIdx.x, tid = threadIdx.x;
    __shared__ float zs[DD];
    __shared__ float att[HW];
    __shared__ float red[16];
    zs[tid] = z[(size_t)b * DD + tid];
    __syncthreads();
    int warp = tid >> 5, lane = tid & 31;
    const float* base = KBp + (size_t)b * HW * DD;
    for (int hw = warp; hw < HW; hw += 16) {
        const float4* row = (const float4*)(base + (size_t)hw * DD);
        const float4* z4p = (const float4*)zs;
        float acc = 0.f;
#pragma unroll
        for (int i = 0; i < 4; i++) {
            float4 kv = row[lane + i * 32];
            float4 zv = z4p[lane + i * 32];
            acc += kv.x * zv.x + kv.y * zv.y + kv.z * zv.z + kv.w * zv.w;
        }
        for (int off = 16; off; off >>= 1) acc += __shfl_down_sync(~0u, acc, off);
        if (lane == 0) att[hw] = acc;
    }
    __syncthreads();
    float val = (tid < HW) ? att[tid] : -1e30f;
    float m = val;
    for (int off = 16; off; off >>= 1) m = fmaxf(m, __shfl_xor_sync(~0u, m, off));
    if (lane == 0) red[warp] = m;
    __syncthreads();
    if (warp == 0) {
        float mm = (lane < 16) ? red[lane] : -1e30f;
        for (int off = 8; off; off >>= 1) mm = fmaxf(mm, __shfl_xor_sync(~0u, mm, off));
        if (lane == 0) red[0] = mm;
    }
    __syncthreads();
    float mx = red[0];
    float e = (tid < HW) ? expf(val - mx) : 0.f;
    float s = e;
    for (int off = 16; off; off >>= 1) s += __shfl_xor_sync(~0u, s, off);
    __syncthreads();
    if (lane == 0) red[warp] = s;
    __syncthreads();
    if (warp == 0) {
        float ss = (lane < 16) ? red[lane] : 0.f;
        for (int off = 8; off; off >>= 1) ss += __shfl_xor_sync(~0u, ss, off);
        if (lane == 0) red[0] = ss;
    }
    __syncthreads();
    float inv = 1.f / red[0];
    if (tid < HW) att[tid] = e * inv;
    __syncthreads();
    // m_new[d] = sum_hw rattn[hw] * KBp[b,hw,d]
    const float* col = base + tid;
    float acc = 0.f;
#pragma unroll 4
    for (int hw = 0; hw < HW; hw++) acc += att[hw] * col[(size_t)hw * DD];
    mnew[(size_t)b * DD + tid] = acc;
}

// ---------------- write unit self-attention (one block per batch, 128 threads) ----------------
__global__ void __launch_bounds__(128)
self_attn_k(const float* __restrict__ chist, const float* __restrict__ mhist,
            const float* __restrict__ wwa, int t, float* __restrict__ msa)
{
    int b = blockIdx.x, tid = threadIdx.x;
    const float* ci = chist + (size_t)(t + 1) * BDSZ + (size_t)b * DD;
    float a0 = ci[tid] * wwa[tid];
    float a1 = ci[tid + 128] * wwa[tid + 128];
    float a2 = ci[tid + 256] * wwa[tid + 256];
    float a3 = ci[tid + 384] * wwa[tid + 384];
    float acc[TT];
#pragma unroll
    for (int tp = 0; tp < TT; tp++) acc[tp] = 0.f;
#pragma unroll
    for (int tp = 0; tp < TT; tp++) {
        if (tp <= t) {
            const float* ch = chist + (size_t)tp * BDSZ + (size_t)b * DD;
            acc[tp] = a0 * ch[tid] + a1 * ch[tid + 128] + a2 * ch[tid + 256] + a3 * ch[tid + 384];
        }
    }
    __shared__ float wred[4][TT];
    int lane = tid & 31, warp = tid >> 5;
#pragma unroll
    for (int tp = 0; tp < TT; tp++) {
        float x = acc[tp];
        for (int off = 16; off; off >>= 1) x += __shfl_down_sync(~0u, x, off);
        if (lane == 0) wred[warp][tp] = x;
    }
    __syncthreads();
    __shared__ float sattn[TT];
    if (tid == 0) {
        int nt = t + 1;
        float slog[TT];
        float mx = -1e30f;
        for (int tp = 0; tp < nt; tp++) {
            float v = wred[0][tp] + wred[1][tp] + wred[2][tp] + wred[3][tp];
            slog[tp] = v;
            mx = fmaxf(mx, v);
        }
        float tot = 0.f;
        for (int tp = 0; tp < nt; tp++) { float ee = expf(slog[tp] - mx); slog[tp] = ee; tot += ee; }
        for (int tp = 0; tp < nt; tp++) sattn[tp] = slog[tp] / tot;
        for (int tp = nt; tp < TT; tp++) sattn[tp] = 0.f;
    }
    __syncthreads();
#pragma unroll
    for (int i = 0; i < 4; i++) {
        int d = tid + i * 128;
        float sv = 0.f;
#pragma unroll
        for (int tp = 0; tp < TT; tp++)
            if (tp <= t) sv += sattn[tp] * mhist[(size_t)tp * BDSZ + (size_t)b * DD + d];
        msa[(size_t)b * DD + d] = sv;
    }
}

// ---------------- host-side launcher helpers ----------------
template<bool WNT, int EPI>
static void launch_gemm(const float* A0, const float* A1, int lda0, int lda1, int K0, int K,
                        const float* W, const float* bias, float* out, int ldo, int N,
                        const float* P1 = nullptr, int ldp1 = 0, const float* P2 = nullptr)
{
    dim3 grid(N / 8, BB / 64);
    gemm_k<WNT, EPI><<<grid, 256>>>(A0, A1, lda0, lda1, K0, K, W, bias, out, ldo, N, P1, ldp1, P2);
}

extern "C" void kernel_launch(void* const* d_in, const int* in_sizes, int n_in,
                              void* d_out, int out_size)
{
    const float* q   = (const float*)d_in[0];
    const float* cws = (const float*)d_in[1];
    const float* KB  = (const float*)d_in[2];
    const float* c0  = (const float*)d_in[3];
    const float* m0  = (const float*)d_in[4];
    const float* Wq  = (const float*)d_in[5];
    const float* bq  = (const float*)d_in[6];
    const float* Wct = (const float*)d_in[7];
    const float* bct = (const float*)d_in[8];
    const float* wca = (const float*)d_in[9];
    // d_in[10] bca: constant in softmax -> unused
    const float* Wm  = (const float*)d_in[11];
    const float* bm  = (const float*)d_in[12];
    const float* Wkb = (const float*)d_in[13];
    // d_in[14] bkb: unused (cancels in softmax)
    const float* Wrm = (const float*)d_in[15];
    // d_in[16] brm, d_in[18] bra: unused (cancel in softmax)
    const float* wra = (const float*)d_in[17];
    const float* Wwm = (const float*)d_in[19];
    const float* bwm = (const float*)d_in[20];
    const float* wwa = (const float*)d_in[21];
    // d_in[22] bwa: unused (cancels in softmax)
    const float* Wam = (const float*)d_in[23];
    const float* bam = (const float*)d_in[24];
    const float* Wg  = (const float*)d_in[25];
    const float* bg  = (const float*)d_in[26];
    // d_in[27] steps == 12 (fixed shape registry)

    float *KBp, *chist, *mhist, *qi, *cq, *v, *mp, *U, *z, *mnew, *m1, *msa, *gbuf;
    cudaGetSymbolAddress((void**)&KBp,   g_KBp);
    cudaGetSymbolAddress((void**)&chist, g_chist);
    cudaGetSymbolAddress((void**)&mhist, g_mhist);
    cudaGetSymbolAddress((void**)&qi,    g_qi);
    cudaGetSymbolAddress((void**)&cq,    g_cq);
    cudaGetSymbolAddress((void**)&v,     g_v);
    cudaGetSymbolAddress((void**)&mp,    g_mp);
    cudaGetSymbolAddress((void**)&U,     g_U);
    cudaGetSymbolAddress((void**)&z,     g_z);
    cudaGetSymbolAddress((void**)&mnew,  g_mnew);
    cudaGetSymbolAddress((void**)&m1,    g_m1);
    cudaGetSymbolAddress((void**)&msa,   g_msa);
    cudaGetSymbolAddress((void**)&gbuf,  g_g);

    // init history slot 0
    cudaMemcpyAsync(chist, c0, BDSZ * sizeof(float), cudaMemcpyDeviceToDevice);
    cudaMemcpyAsync(mhist, m0, BDSZ * sizeof(float), cudaMemcpyDeviceToDevice);

    // precompute: KBp transpose + q_i
    transpose_kb_k<<<dim3((HW + 31) / 32, DD / 32, BB), dim3(32, 8)>>>(KB, KBp);
    launch_gemm<false, 0>(q, nullptr, DD, DD, DD, DD, Wq, bq, qi, DD, DD);

    for (int t = 0; t < TT; t++) {
        const float* chist_t  = chist + (size_t)t * BDSZ;
        const float* mhist_t  = mhist + (size_t)t * BDSZ;
        float*       chist_t1 = chist + (size_t)(t + 1) * BDSZ;
        float*       mhist_t1 = mhist + (size_t)(t + 1) * BDSZ;

        // cq = [q_i, c_prev] @ Wct + bct
        launch_gemm<false, 0>(qi, chist_t, DD, DD, DD, 2 * DD, Wct, bct, cq, DD, DD);
        // mp = m_prev @ Wm + bm
        launch_gemm<false, 0>(mhist_t, nullptr, DD, DD, DD, DD, Wm, bm, mp, DD, DD);
        // control attention -> c_i (stored at chist[t+1]) and v = c_i*wra
        control_attn_k<<<BB, 128>>>(cq, cws, wca, wra, chist_t1, v);
        // U = v @ Wrm^T ; epilogue: cols<512 *= mp  (-> y | u2)
        launch_gemm<true, 2>(v, nullptr, DD, DD, DD, DD, Wrm, nullptr, U, 2 * DD, 2 * DD, mp, DD);
        // g = sigmoid(c_i @ Wg + bg)
        launch_gemm<false, 1>(chist_t1, nullptr, DD, DD, DD, DD, Wg, bg, gbuf, DD, DD);
        // self-attention over history -> m_sa
        self_attn_k<<<BB, 128>>>(chist, mhist, wwa, t, msa);
        // z = y @ Wkb^T + u2
        launch_gemm<true, 3>(U, nullptr, 2 * DD, 2 * DD, DD, DD, Wkb, nullptr, z, DD, DD, U + DD, 2 * DD);
        // read attention -> m_new
        read_attn_k<<<BB, 512>>>(KBp, z, mnew);
        // _m1 = [m_new, m_prev] @ Wwm + bwm
        launch_gemm<false, 0>(mnew, mhist_t, DD, DD, DD, 2 * DD, Wwm, bwm, m1, DD, DD);
        // m_next = g*m_prev + (1-g)*([m_sa,_m1]@Wam + bam)  -> mhist[t+1]
        launch_gemm<false, 4>(msa, m1, DD, DD, DD, 2 * DD, Wam, bam, mhist_t1, DD, DD, gbuf, DD, mhist_t);
    }

    cudaMemcpyAsync(d_out, mhist + (size_t)TT * BDSZ, BDSZ * sizeof(float),
                    cudaMemcpyDeviceToDevice);
}

// round 3
// speedup vs baseline: 1.3417x; 1.3417x over previous
#include <cuda_runtime.h>
#include <math.h>

// ---------------- problem constants (fixed shapes) ----------------
#define BB   128
#define DD   512
#define SS   30
#define HW   196
#define TT   12
#define NH   13
#define BDSZ (BB*DD)

// ---------------- device scratch ----------------
__device__ float g_KBp[(size_t)BB*HW*DD];
__device__ float g_chist[(size_t)NH*BDSZ];
__device__ float g_mhist[(size_t)NH*BDSZ];
__device__ float g_qi[BDSZ];
__device__ float g_cq0[BDSZ];
__device__ float g_cq[BDSZ];
__device__ float g_v[BDSZ];
__device__ float g_mp[BDSZ];
__device__ float g_U[(size_t)BB*2*DD];
__device__ float g_z[BDSZ];
__device__ float g_mnew[BDSZ];
__device__ float g_msa[BDSZ];
__device__ float g_g[BDSZ];
__device__ float g_Wcomb[(size_t)3*DD*DD];   // 1536 x 512
__device__ float g_bcomb[DD];

// ---------------- GEMM problem descriptor ----------------
struct GProb {
    const float* A0; const float* A1; const float* A2;
    int lda0, lda1, lda2;
    int K0, K01, K;            // segment boundaries (multiples of 512), total K
    const float* W; int wtrans; // 0: W is (K,N) row-major; 1: W is (N,K) row-major
    const float* bias;
    float* out; int ldo; int N; int M;
    const float* P1; int ldp1;
    const float* P2;
    int epi;  // 0:+bias(opt) 1:sigmoid(+bias) 2:mul P1 if c<ldp1 3:+P1 4:gate
};

// ---------------- tiled GEMM: out(M x N) = [A0|A1|A2] * W, 64x32 tile ----------------
__global__ void __launch_bounds__(256)
gemm2_k(const GProb p0, const GProb p1)
{
    const GProb P = (blockIdx.z == 0) ? p0 : p1;
    int n0 = blockIdx.x * 32;
    int r0 = blockIdx.y * 64;
    if (n0 >= P.N || r0 >= P.M) return;

    __shared__ float As[2][16][68];
    __shared__ float Bs[2][16][36];

    int tid = threadIdx.x;
    int tx = tid & 15, ty = tid >> 4;      // tx: 16 N-groups (2 cols), ty: 16 M-groups (4 rows)
    int akk = tid & 15, am = tid >> 4;     // A load mapping
    float ar[4], br[2];
    float acc[4][2];
#pragma unroll
    for (int i = 0; i < 4; i++) { acc[i][0] = 0.f; acc[i][1] = 0.f; }

    int ntiles = P.K / 16;

    // stage tile 0
    {
        const float* ap = P.A0 + (size_t)(r0 + am) * P.lda0 + akk;
#pragma unroll
        for (int j = 0; j < 4; j++) ar[j] = ap[(size_t)(16 * j) * P.lda0];
        if (P.wtrans) {
            const float* wp = P.W + (size_t)(n0 + am) * P.K + akk;
            br[0] = wp[0]; br[1] = wp[(size_t)16 * P.K];
        } else {
            int n = tid & 31, kb = tid >> 5;
            const float* wp = P.W + (size_t)kb * P.N + n0 + n;
            br[0] = wp[0]; br[1] = wp[(size_t)8 * P.N];
        }
#pragma unroll
        for (int j = 0; j < 4; j++) As[0][akk][am + 16 * j] = ar[j];
        if (P.wtrans) { Bs[0][akk][am] = br[0]; Bs[0][akk][am + 16] = br[1]; }
        else { int n = tid & 31, kb = tid >> 5; Bs[0][kb][n] = br[0]; Bs[0][kb + 8][n] = br[1]; }
    }
    __syncthreads();

    for (int kt = 0; kt < ntiles; kt++) {
        int cur = kt & 1;
        if (kt + 1 < ntiles) {
            int k0 = (kt + 1) * 16;
            const float* Ab; int lda; int koff;
            if (k0 < P.K0)       { Ab = P.A0; lda = P.lda0; koff = k0 + akk; }
            else if (k0 < P.K01) { Ab = P.A1; lda = P.lda1; koff = k0 + akk - P.K0; }
            else                 { Ab = P.A2; lda = P.lda2; koff = k0 + akk - P.K01; }
            const float* ap = Ab + (size_t)(r0 + am) * lda + koff;
#pragma unroll
            for (int j = 0; j < 4; j++) ar[j] = ap[(size_t)(16 * j) * lda];
            if (P.wtrans) {
                const float* wp = P.W + (size_t)(n0 + am) * P.K + k0 + akk;
                br[0] = wp[0]; br[1] = wp[(size_t)16 * P.K];
            } else {
                int n = tid & 31, kb = tid >> 5;
                const float* wp = P.W + (size_t)(k0 + kb) * P.N + n0 + n;
                br[0] = wp[0]; br[1] = wp[(size_t)8 * P.N];
            }
        }
#pragma unroll
        for (int kk = 0; kk < 16; kk++) {
            float4 a4 = *(const float4*)&As[cur][kk][ty * 4];
            float2 b2 = *(const float2*)&Bs[cur][kk][tx * 2];
            acc[0][0] += a4.x * b2.x; acc[0][1] += a4.x * b2.y;
            acc[1][0] += a4.y * b2.x; acc[1][1] += a4.y * b2.y;
            acc[2][0] += a4.z * b2.x; acc[2][1] += a4.z * b2.y;
            acc[3][0] += a4.w * b2.x; acc[3][1] += a4.w * b2.y;
        }
        if (kt + 1 < ntiles) {
            int nxt = cur ^ 1;
#pragma unroll
            for (int j = 0; j < 4; j++) As[nxt][akk][am + 16 * j] = ar[j];
            if (P.wtrans) { Bs[nxt][akk][am] = br[0]; Bs[nxt][akk][am + 16] = br[1]; }
            else { int n = tid & 31, kb = tid >> 5; Bs[nxt][kb][n] = br[0]; Bs[nxt][kb + 8][n] = br[1]; }
            __syncthreads();
        }
    }

    int rg0 = r0 + ty * 4;
    int c0 = n0 + tx * 2;
#pragma unroll
    for (int i = 0; i < 4; i++) {
        int rg = rg0 + i;
        float v0 = acc[i][0], v1 = acc[i][1];
        if (P.epi == 0) {
            if (P.bias) { v0 += P.bias[c0]; v1 += P.bias[c0 + 1]; }
        } else if (P.epi == 1) {
            v0 += P.bias[c0]; v1 += P.bias[c0 + 1];
            v0 = 1.f / (1.f + expf(-v0)); v1 = 1.f / (1.f + expf(-v1));
        } else if (P.epi == 2) {
            if (c0 < P.ldp1) {
                v0 *= P.P1[(size_t)rg * P.ldp1 + c0];
                v1 *= P.P1[(size_t)rg * P.ldp1 + c0 + 1];
            }
        } else if (P.epi == 3) {
            v0 += P.P1[(size_t)rg * P.ldp1 + c0];
            v1 += P.P1[(size_t)rg * P.ldp1 + c0 + 1];
        } else { // gate
            float m20 = v0 + P.bias[c0], m21 = v1 + P.bias[c0 + 1];
            float g0 = P.P1[(size_t)rg * P.ldp1 + c0], g1 = P.P1[(size_t)rg * P.ldp1 + c0 + 1];
            float q0 = P.P2[(size_t)rg * P.ldp1 + c0], q1 = P.P2[(size_t)rg * P.ldp1 + c0 + 1];
            v0 = g0 * q0 + (1.f - g0) * m20;
            v1 = g1 * q1 + (1.f - g1) * m21;
        }
        *(float2*)&P.out[(size_t)rg * P.ldo + c0] = make_float2(v0, v1);
    }
}

// ---------------- transpose KB (B,D,HW) -> KBp (B,HW,D) ----------------
__global__ void transpose_kb_k(const float* __restrict__ KB, float* __restrict__ KBp)
{
    __shared__ float tile[32][33];
    int b = blockIdx.z;
    int hw0 = blockIdx.x * 32, d0 = blockIdx.y * 32;
    int tx = threadIdx.x, ty = threadIdx.y;
    const float* src = KB + (size_t)b * DD * HW;
#pragma unroll
    for (int j = 0; j < 4; j++) {
        int d = d0 + ty + j * 8;
        int hw = hw0 + tx;
        if (hw < HW) tile[ty + j * 8][tx] = src[(size_t)d * HW + hw];
    }
    __syncthreads();
    float* dst = KBp + (size_t)b * HW * DD;
#pragma unroll
    for (int j = 0; j < 4; j++) {
        int hw = hw0 + ty + j * 8;
        if (hw < HW) dst[(size_t)hw * DD + d0 + tx] = tile[tx][ty + j * 8];
    }
}

// ---------------- merged control + write-self attention (one block per batch) ----------------
__global__ void __launch_bounds__(128)
attn1_k(const float* __restrict__ cq, const float* __restrict__ cws,
        const float* __restrict__ wca, const float* __restrict__ wra,
        const float* __restrict__ wwa,
        float* __restrict__ chist, const float* __restrict__ mhist, int t,
        float* __restrict__ v, float* __restrict__ msa)
{
    int b = blockIdx.x, tid = threadIdx.x;
    int lane = tid & 31, warp = tid >> 5;

    // ---- control attention ----
    float accs[SS];
#pragma unroll
    for (int s = 0; s < SS; s++) accs[s] = 0.f;
#pragma unroll
    for (int i = 0; i < 4; i++) {
        int d = tid + i * 128;
        float a = cq[(size_t)b * DD + d] * wca[d];
        const float* row = cws + ((size_t)b * DD + d) * SS;
#pragma unroll
        for (int s = 0; s < SS; s++) accs[s] += a * row[s];
    }
    __shared__ float wred[4][SS];
#pragma unroll
    for (int s = 0; s < SS; s++) {
        float x = accs[s];
        for (int off = 16; off; off >>= 1) x += __shfl_down_sync(~0u, x, off);
        if (lane == 0) wred[warp][s] = x;
    }
    __syncthreads();
    __shared__ float cattn[SS];
    if (warp == 0) {
        float val = (lane < SS) ? (wred[0][lane] + wred[1][lane] + wred[2][lane] + wred[3][lane]) : -1e30f;
        float mx = val;
        for (int off = 16; off; off >>= 1) mx = fmaxf(mx, __shfl_xor_sync(~0u, mx, off));
        float e = (lane < SS) ? expf(val - mx) : 0.f;
        float tot = e;
        for (int off = 16; off; off >>= 1) tot += __shfl_xor_sync(~0u, tot, off);
        if (lane < SS) cattn[lane] = e / tot;
    }
    __syncthreads();

    float ci[4];
#pragma unroll
    for (int i = 0; i < 4; i++) {
        int d = tid + i * 128;
        const float* row = cws + ((size_t)b * DD + d) * SS;
        float c = 0.f;
#pragma unroll
        for (int s = 0; s < SS; s++) c += cattn[s] * row[s];
        ci[i] = c;
        chist[(size_t)(t + 1) * BDSZ + (size_t)b * DD + d] = c;
        v[(size_t)b * DD + d] = c * wra[d];
    }

    // ---- write-unit self attention over history 0..t ----
    float aw[4];
#pragma unroll
    for (int i = 0; i < 4; i++) aw[i] = ci[i] * wwa[tid + i * 128];

    float acct[TT];
#pragma unroll
    for (int tp = 0; tp < TT; tp++) acct[tp] = 0.f;
#pragma unroll
    for (int tp = 0; tp < TT; tp++) {
        if (tp <= t) {
            const float* ch = chist + (size_t)tp * BDSZ + (size_t)b * DD;
            acct[tp] = aw[0] * ch[tid] + aw[1] * ch[tid + 128]
                     + aw[2] * ch[tid + 256] + aw[3] * ch[tid + 384];
        }
    }
    __shared__ float wred2[4][TT];
#pragma unroll
    for (int tp = 0; tp < TT; tp++) {
        float x = acct[tp];
        for (int off = 16; off; off >>= 1) x += __shfl_down_sync(~0u, x, off);
        if (lane == 0) wred2[warp][tp] = x;
    }
    __syncthreads();
    __shared__ float sattn[TT];
    if (tid == 0) {
        int nt = t + 1;
        float slog[TT];
        float mx = -1e30f;
        for (int tp = 0; tp < nt; tp++) {
            float vv = wred2[0][tp] + wred2[1][tp] + wred2[2][tp] + wred2[3][tp];
            slog[tp] = vv;
            mx = fmaxf(mx, vv);
        }
        float tot = 0.f;
        for (int tp = 0; tp < nt; tp++) { float ee = expf(slog[tp] - mx); slog[tp] = ee; tot += ee; }
        for (int tp = 0; tp < nt; tp++) sattn[tp] = slog[tp] / tot;
        for (int tp = nt; tp < TT; tp++) sattn[tp] = 0.f;
    }
    __syncthreads();
#pragma unroll
    for (int i = 0; i < 4; i++) {
        int d = tid + i * 128;
        float sv = 0.f;
#pragma unroll
        for (int tp = 0; tp < TT; tp++)
            if (tp <= t) sv += sattn[tp] * mhist[(size_t)tp * BDSZ + (size_t)b * DD + d];
        msa[(size_t)b * DD + d] = sv;
    }
}

// ---------------- read unit attention (one block per batch, 512 threads) ----------------
__global__ void __launch_bounds__(512)
read_attn_k(const float* __restrict__ KBp, const float* __restrict__ z,
            float* __restrict__ mnew)
{
    int b = blockIdx.x, tid = threadIdx.x;
    __shared__ float zs[DD];
    __shared__ float att[HW];
    __shared__ float red[16];
    zs[tid] = z[(size_t)b * DD + tid];
    __syncthreads();
    int warp = tid >> 5, lane = tid & 31;
    const float* base = KBp + (size_t)b * HW * DD;
    for (int hw = warp; hw < HW; hw += 16) {
        const float4* row = (const float4*)(base + (size_t)hw * DD);
        const float4* z4p = (const float4*)zs;
        float acc = 0.f;
#pragma unroll
        for (int i = 0; i < 4; i++) {
            float4 kv = row[lane + i * 32];
            float4 zv = z4p[lane + i * 32];
            acc += kv.x * zv.x + kv.y * zv.y + kv.z * zv.z + kv.w * zv.w;
        }
        for (int off = 16; off; off >>= 1) acc += __shfl_down_sync(~0u, acc, off);
        if (lane == 0) att[hw] = acc;
    }
    __syncthreads();
    float val = (tid < HW) ? att[tid] : -1e30f;
    float m = val;
    for (int off = 16; off; off >>= 1) m = fmaxf(m, __shfl_xor_sync(~0u, m, off));
    if (lane == 0) red[warp] = m;
    __syncthreads();
    if (warp == 0) {
        float mm = (lane < 16) ? red[lane] : -1e30f;
        for (int off = 8; off; off >>= 1) mm = fmaxf(mm, __shfl_xor_sync(~0u, mm, off));
        if (lane == 0) red[0] = mm;
    }
    __syncthreads();
    float mx = red[0];
    float e = (tid < HW) ? expf(val - mx) : 0.f;
    float s = e;
    for (int off = 16; off; off >>= 1) s += __shfl_xor_sync(~0u, s, off);
    __syncthreads();
    if (lane == 0) red[warp] = s;
    __syncthreads();
    if (warp == 0) {
        float ss = (lane < 16) ? red[lane] : 0.f;
        for (int off = 8; off; off >>= 1) ss += __shfl_xor_sync(~0u, ss, off);
        if (lane == 0) red[0] = ss;
    }
    __syncthreads();
    float inv = 1.f / red[0];
    if (tid < HW) att[tid] = e * inv;
    __syncthreads();
    const float* col = base + tid;
    float acc = 0.f;
#pragma unroll 4
    for (int hw = 0; hw < HW; hw++) acc += att[hw] * col[(size_t)hw * DD];
    mnew[(size_t)b * DD + tid] = acc;
}

// ---------------- bcomb = bwm @ Wam_bot + bam ----------------
__global__ void bcomb_k(const float* __restrict__ Wam, const float* __restrict__ bwm,
                        const float* __restrict__ bam, float* __restrict__ bcomb)
{
    int n = blockIdx.x * 128 + threadIdx.x;
    float s = bam[n];
    for (int j = 0; j < DD; j++) s += bwm[j] * Wam[(size_t)(DD + j) * DD + n];
    bcomb[n] = s;
}

// ---------------- host ----------------
static GProb mk(const float* A0, int lda0, int K, const float* W, int wtrans,
                const float* bias, float* out, int ldo, int N, int M, int epi,
                const float* P1 = nullptr, int ldp1 = 0, const float* P2 = nullptr)
{
    GProb p;
    p.A0 = A0; p.A1 = nullptr; p.A2 = nullptr;
    p.lda0 = lda0; p.lda1 = 0; p.lda2 = 0;
    p.K0 = K; p.K01 = K; p.K = K;
    p.W = W; p.wtrans = wtrans; p.bias = bias;
    p.out = out; p.ldo = ldo; p.N = N; p.M = M;
    p.P1 = P1; p.ldp1 = ldp1; p.P2 = P2; p.epi = epi;
    return p;
}

static void run1(const GProb& a)
{
    dim3 g(a.N / 32, a.M / 64, 1);
    gemm2_k<<<g, 256>>>(a, a);
}
static void run2(const GProb& a, const GProb& b)
{
    int nb = (a.N > b.N ? a.N : b.N) / 32;
    dim3 g(nb, 2, 2);
    gemm2_k<<<g, 256>>>(a, b);
}

extern "C" void kernel_launch(void* const* d_in, const int* in_sizes, int n_in,
                              void* d_out, int out_size)
{
    const float* q   = (const float*)d_in[0];
    const float* cws = (const float*)d_in[1];
    const float* KB  = (const float*)d_in[2];
    const float* c0  = (const float*)d_in[3];
    const float* m0  = (const float*)d_in[4];
    const float* Wq  = (const float*)d_in[5];
    const float* bq  = (const float*)d_in[6];
    const float* Wct = (const float*)d_in[7];
    const float* bct = (const float*)d_in[8];
    const float* wca = (const float*)d_in[9];
    const float* Wm  = (const float*)d_in[11];
    const float* bm  = (const float*)d_in[12];
    const float* Wkb = (const float*)d_in[13];
    const float* Wrm = (const float*)d_in[15];
    const float* wra = (const float*)d_in[17];
    const float* Wwm = (const float*)d_in[19];
    const float* bwm = (const float*)d_in[20];
    const float* wwa = (const float*)d_in[21];
    const float* Wam = (const float*)d_in[23];
    const float* bam = (const float*)d_in[24];
    const float* Wg  = (const float*)d_in[25];
    const float* bg  = (const float*)d_in[26];

    float *KBp, *chist, *mhist, *qi, *cq0, *cq, *v, *mp, *U, *z, *mnew, *msa, *gbuf, *Wcomb, *bcomb;
    cudaGetSymbolAddress((void**)&KBp,   g_KBp);
    cudaGetSymbolAddress((void**)&chist, g_chist);
    cudaGetSymbolAddress((void**)&mhist, g_mhist);
    cudaGetSymbolAddress((void**)&qi,    g_qi);
    cudaGetSymbolAddress((void**)&cq0,   g_cq0);
    cudaGetSymbolAddress((void**)&cq,    g_cq);
    cudaGetSymbolAddress((void**)&v,     g_v);
    cudaGetSymbolAddress((void**)&mp,    g_mp);
    cudaGetSymbolAddress((void**)&U,     g_U);
    cudaGetSymbolAddress((void**)&z,     g_z);
    cudaGetSymbolAddress((void**)&mnew,  g_mnew);
    cudaGetSymbolAddress((void**)&msa,   g_msa);
    cudaGetSymbolAddress((void**)&gbuf,  g_g);
    cudaGetSymbolAddress((void**)&Wcomb, g_Wcomb);
    cudaGetSymbolAddress((void**)&bcomb, g_bcomb);

    // ---- setup ----
    cudaMemcpyAsync(chist, c0, BDSZ * sizeof(float), cudaMemcpyDeviceToDevice);
    cudaMemcpyAsync(mhist, m0, BDSZ * sizeof(float), cudaMemcpyDeviceToDevice);
    cudaMemcpyAsync(Wcomb, Wam, (size_t)DD * DD * sizeof(float), cudaMemcpyDeviceToDevice);

    transpose_kb_k<<<dim3((HW + 31) / 32, DD / 32, BB), dim3(32, 8)>>>(KB, KBp);
    bcomb_k<<<4, 128>>>(Wam, bwm, bam, bcomb);

    // qi = q @ Wq + bq
    run1(mk(q, DD, DD, Wq, 0, bq, qi, DD, DD, BB, 0));
    // cq0 = qi @ Wct_top + bct
    run1(mk(qi, DD, DD, Wct, 0, bct, cq0, DD, DD, BB, 0));
    // Wcomb rows 512..1535 = Wwm @ Wam_bot   (M = 1024)
    run1(mk(Wwm, DD, DD, Wam + (size_t)DD * DD, 0, nullptr,
            Wcomb + (size_t)DD * DD, DD, DD, 2 * DD, 0));

    for (int t = 0; t < TT; t++) {
        const float* chist_t  = chist + (size_t)t * BDSZ;
        const float* mhist_t  = mhist + (size_t)t * BDSZ;
        float*       chist_t1 = chist + (size_t)(t + 1) * BDSZ;
        float*       mhist_t1 = mhist + (size_t)(t + 1) * BDSZ;

        // k1: cq = c_prev @ Wct_bot + cq0   ||   mp = m_prev @ Wm + bm
        {
            GProb pa = mk(chist_t, DD, DD, Wct + (size_t)DD * DD, 0, nullptr,
                          cq, DD, DD, BB, 3, cq0, DD);
            GProb pb = mk(mhist_t, DD, DD, Wm, 0, bm, mp, DD, DD, BB, 0);
            run2(pa, pb);
        }
        // merged control + self attention
        attn1_k<<<BB, 128>>>(cq, cws, wca, wra, wwa, chist, mhist, t, v, msa);
        // k2: U = v @ Wrm^T (cols<512 *= mp)   ||   g = sigmoid(c_i @ Wg + bg)
        {
            GProb pa = mk(v, DD, DD, Wrm, 1, nullptr, U, 2 * DD, 2 * DD, BB, 2, mp, DD);
            GProb pb = mk(chist_t1, DD, DD, Wg, 0, bg, gbuf, DD, DD, BB, 1);
            run2(pa, pb);
        }
        // k3: z = y @ Wkb^T + u2
        run1(mk(U, 2 * DD, DD, Wkb, 1, nullptr, z, DD, DD, BB, 3, U + DD, 2 * DD));
        // read attention -> m_new
        read_attn_k<<<BB, 512>>>(KBp, z, mnew);
        // k5: m_next = gate( [m_sa | m_new | m_prev] @ Wcomb + bcomb )
        {
            GProb p = mk(msa, DD, 3 * DD, Wcomb, 0, bcomb, mhist_t1, DD, DD, BB, 4,
                         gbuf, DD, mhist_t);
            p.A1 = mnew; p.lda1 = DD;
            p.A2 = mhist_t; p.lda2 = DD;
            p.K0 = DD; p.K01 = 2 * DD;
            run1(p);
        }
    }

    cudaMemcpyAsync(d_out, mhist + (size_t)TT * BDSZ, BDSZ * sizeof(float),
                    cudaMemcpyDeviceToDevice);
}

// round 4
// speedup vs baseline: 2.3462x; 1.7486x over previous
#include <cuda_runtime.h>
#include <math.h>

// ---------------- problem constants (fixed shapes) ----------------
#define BB   128
#define DD   512
#define SS   30
#define HW   196
#define TT   12
#define NH   13
#define BDSZ (BB*DD)

// ---------------- device scratch ----------------
__device__ float g_KBp[(size_t)BB*HW*DD];
__device__ float g_chist[(size_t)NH*BDSZ];
__device__ float g_mhist[(size_t)NH*BDSZ];
__device__ float g_qi[BDSZ];
__device__ float g_cq0[BDSZ];
__device__ float g_v[BDSZ];
__device__ float g_U[(size_t)BB*2*DD];
__device__ float g_mnew[BDSZ];
__device__ float g_msa[BDSZ];
__device__ float g_Wcomb[(size_t)3*DD*DD];   // 1536 x 512
__device__ float g_bcomb[DD];
// split-K partial buffers: layout [kchunk][M][N]
__device__ float g_p_cq[(size_t)4*BDSZ];
__device__ float g_p_mp[(size_t)4*BDSZ];
__device__ float g_p_U [(size_t)4*BB*2*DD];
__device__ float g_p_g [(size_t)4*BDSZ];
__device__ float g_p_z [(size_t)8*BDSZ];
__device__ float g_p_f [(size_t)12*BDSZ];
__device__ float g_p_set[(size_t)4*1024*DD];

// ---------------- GEMM problem descriptor ----------------
struct GP {
    const float* A0; const float* A1; const float* A2;
    int lda0, lda1, lda2;
    int K0, K01, K;           // segment bounds (global k), total K
    const float* W; int wtrans; int ldw;
    float* part;              // [kchunks][M][N]
    int M, N, KC;             // KC = k per chunk
};

// ---------------- split-K partial GEMM: 128x32 tile, thread 4m x 4n ----------------
__global__ void __launch_bounds__(256)
gpartial_k(const GP q0, const GP q1)
{
    const GP P = (blockIdx.z == 0) ? q0 : q1;
    int ntiles = P.N >> 5;
    int nt = blockIdx.x % ntiles;
    int mt = blockIdx.x / ntiles;
    int m0 = mt * 128;
    if (m0 >= P.M) return;
    int kbase = blockIdx.y * P.KC;
    if (kbase >= P.K) return;
    int n0 = nt * 32;

    __shared__ float As[16][132];   // [kk][m], float4-readable
    __shared__ float Ws[16][36];    // [kk][n]

    int tid = threadIdx.x;
    int tx = tid & 7;          // n quad: n = n0 + tx*4
    int tg = tid >> 3;         // m quad: m = m0 + tg*4
    int lm = tid >> 1;         // A-loader row 0..127
    int lk = (tid & 1) * 8;    // A-loader k offset 0/8

    float acc[4][4];
#pragma unroll
    for (int i = 0; i < 4; i++)
#pragma unroll
        for (int j = 0; j < 4; j++) acc[i][j] = 0.f;

    for (int kt = 0; kt < P.KC; kt += 16) {
        int k0 = kbase + kt;
        // A segment select
        const float* Ab; int lda; int koff;
        if (k0 < P.K0)       { Ab = P.A0; lda = P.lda0; koff = k0; }
        else if (k0 < P.K01) { Ab = P.A1; lda = P.lda1; koff = k0 - P.K0; }
        else                 { Ab = P.A2; lda = P.lda2; koff = k0 - P.K01; }
        const float* ap = Ab + (size_t)(m0 + lm) * lda + koff + lk;
        float4 a0 = *(const float4*)ap;
        float4 a1 = *(const float4*)(ap + 4);
        // W loads
        float w0, w1;
        if (P.wtrans) {
            int n = tid >> 3, kk = (tid & 7) * 2;
            const float* wp = P.W + (size_t)(n0 + n) * P.ldw + k0 + kk;
            w0 = wp[0]; w1 = wp[1];
        } else {
            int kk = tid >> 4, n = tid & 15;
            const float* wp = P.W + (size_t)(k0 + kk) * P.ldw + n0 + n;
            w0 = wp[0]; w1 = wp[16];
        }
        __syncthreads();
        As[lk + 0][lm] = a0.x; As[lk + 1][lm] = a0.y;
        As[lk + 2][lm] = a0.z; As[lk + 3][lm] = a0.w;
        As[lk + 4][lm] = a1.x; As[lk + 5][lm] = a1.y;
        As[lk + 6][lm] = a1.z; As[lk + 7][lm] = a1.w;
        if (P.wtrans) {
            int n = tid >> 3, kk = (tid & 7) * 2;
            Ws[kk][n] = w0; Ws[kk + 1][n] = w1;
        } else {
            int kk = tid >> 4, n = tid & 15;
            Ws[kk][n] = w0; Ws[kk][n + 16] = w1;
        }
        __syncthreads();
#pragma unroll
        for (int kk = 0; kk < 16; kk++) {
            float4 a = *(const float4*)&As[kk][tg * 4];
            float4 w = *(const float4*)&Ws[kk][tx * 4];
            acc[0][0] += a.x * w.x; acc[0][1] += a.x * w.y; acc[0][2] += a.x * w.z; acc[0][3] += a.x * w.w;
            acc[1][0] += a.y * w.x; acc[1][1] += a.y * w.y; acc[1][2] += a.y * w.z; acc[1][3] += a.y * w.w;
            acc[2][0] += a.z * w.x; acc[2][1] += a.z * w.y; acc[2][2] += a.z * w.z; acc[2][3] += a.z * w.w;
            acc[3][0] += a.w * w.x; acc[3][1] += a.w * w.y; acc[3][2] += a.w * w.z; acc[3][3] += a.w * w.w;
        }
    }

    float* po = P.part + ((size_t)blockIdx.y * P.M + m0 + tg * 4) * P.N + n0 + tx * 4;
#pragma unroll
    for (int i = 0; i < 4; i++)
        *(float4*)(po + (size_t)i * P.N) = make_float4(acc[i][0], acc[i][1], acc[i][2], acc[i][3]);
}

// ---------------- generic reduce: out = sum_ch part + bias? ----------------
__global__ void reduce0_k(const float* __restrict__ part, int nch, int MN, int N,
                          const float* __restrict__ bias, float* __restrict__ out)
{
    int idx = blockIdx.x * 256 + threadIdx.x;
    if (idx >= MN) return;
    float s = 0.f;
    for (int c = 0; c < nch; c++) s += part[(size_t)c * MN + idx];
    if (bias) s += bias[idx % N];
    out[idx] = s;
}

// ---------------- reduce U (4 chunks) with mp epilogue: cols<512 *= (sum mp + bm) ----------------
__global__ void reduceU_k(const float* __restrict__ pU, const float* __restrict__ pmp,
                          const float* __restrict__ bm, float* __restrict__ U)
{
    const int MN = BB * 2 * DD;
    int idx = blockIdx.x * 256 + threadIdx.x;
    if (idx >= MN) return;
    int n = idx & 1023, m = idx >> 10;
    float s = pU[idx] + pU[MN + idx] + pU[2 * MN + idx] + pU[3 * MN + idx];
    if (n < DD) {
        int j = m * DD + n;
        float mps = pmp[j] + pmp[BDSZ + j] + pmp[2 * BDSZ + j] + pmp[3 * BDSZ + j] + bm[n];
        s *= mps;
    }
    U[idx] = s;
}

// ---------------- reduce final (12 chunks) + gate ----------------
__global__ void reduceF_k(const float* __restrict__ pf, const float* __restrict__ pg,
                          const float* __restrict__ bg, const float* __restrict__ bcomb,
                          const float* __restrict__ mprev, float* __restrict__ mnext)
{
    int idx = blockIdx.x * 256 + threadIdx.x;
    if (idx >= BDSZ) return;
    int n = idx & 511;
    float m2 = bcomb[n];
#pragma unroll
    for (int c = 0; c < 12; c++) m2 += pf[(size_t)c * BDSZ + idx];
    float gs = pg[idx] + pg[BDSZ + idx] + pg[2 * BDSZ + idx] + pg[3 * BDSZ + idx] + bg[n];
    float g = 1.f / (1.f + expf(-gs));
    mnext[idx] = g * mprev[idx] + (1.f - g) * m2;
}

// ---------------- transpose KB (B,D,HW) -> KBp (B,HW,D) ----------------
__global__ void transpose_kb_k(const float* __restrict__ KB, float* __restrict__ KBp)
{
    __shared__ float tile[32][33];
    int b = blockIdx.z;
    int hw0 = blockIdx.x * 32, d0 = blockIdx.y * 32;
    int tx = threadIdx.x, ty = threadIdx.y;
    const float* src = KB + (size_t)b * DD * HW;
#pragma unroll
    for (int j = 0; j < 4; j++) {
        int d = d0 + ty + j * 8;
        int hw = hw0 + tx;
        if (hw < HW) tile[ty + j * 8][tx] = src[(size_t)d * HW + hw];
    }
    __syncthreads();
    float* dst = KBp + (size_t)b * HW * DD;
#pragma unroll
    for (int j = 0; j < 4; j++) {
        int hw = hw0 + ty + j * 8;
        if (hw < HW) dst[(size_t)hw * DD + d0 + tx] = tile[tx][ty + j * 8];
    }
}

// ---------------- merged control + write-self attention (sums cq partials inline) ----------------
__global__ void __launch_bounds__(128)
attn1_k(const float* __restrict__ pcq, const float* __restrict__ cq0,
        const float* __restrict__ cws,
        const float* __restrict__ wca, const float* __restrict__ wra,
        const float* __restrict__ wwa,
        float* __restrict__ chist, const float* __restrict__ mhist, int t,
        float* __restrict__ v, float* __restrict__ msa)
{
    int b = blockIdx.x, tid = threadIdx.x;
    int lane = tid & 31, warp = tid >> 5;

    // ---- control attention ----
    float accs[SS];
#pragma unroll
    for (int s = 0; s < SS; s++) accs[s] = 0.f;
#pragma unroll
    for (int i = 0; i < 4; i++) {
        int d = tid + i * 128;
        size_t j = (size_t)b * DD + d;
        float cqv = pcq[j] + pcq[BDSZ + j] + pcq[2 * BDSZ + j] + pcq[3 * BDSZ + j] + cq0[j];
        float a = cqv * wca[d];
        const float* row = cws + j * SS;
#pragma unroll
        for (int s = 0; s < SS; s++) accs[s] += a * row[s];
    }
    __shared__ float wred[4][SS];
#pragma unroll
    for (int s = 0; s < SS; s++) {
        float x = accs[s];
        for (int off = 16; off; off >>= 1) x += __shfl_down_sync(~0u, x, off);
        if (lane == 0) wred[warp][s] = x;
    }
    __syncthreads();
    __shared__ float cattn[SS];
    if (warp == 0) {
        float val = (lane < SS) ? (wred[0][lane] + wred[1][lane] + wred[2][lane] + wred[3][lane]) : -1e30f;
        float mx = val;
        for (int off = 16; off; off >>= 1) mx = fmaxf(mx, __shfl_xor_sync(~0u, mx, off));
        float e = (lane < SS) ? expf(val - mx) : 0.f;
        float tot = e;
        for (int off = 16; off; off >>= 1) tot += __shfl_xor_sync(~0u, tot, off);
        if (lane < SS) cattn[lane] = e / tot;
    }
    __syncthreads();

    float ci[4];
#pragma unroll
    for (int i = 0; i < 4; i++) {
        int d = tid + i * 128;
        const float* row = cws + ((size_t)b * DD + d) * SS;
        float c = 0.f;
#pragma unroll
        for (int s = 0; s < SS; s++) c += cattn[s] * row[s];
        ci[i] = c;
        chist[(size_t)(t + 1) * BDSZ + (size_t)b * DD + d] = c;
        v[(size_t)b * DD + d] = c * wra[d];
    }

    // ---- write-unit self attention over history 0..t ----
    float aw[4];
#pragma unroll
    for (int i = 0; i < 4; i++) aw[i] = ci[i] * wwa[tid + i * 128];

    float acct[TT];
#pragma unroll
    for (int tp = 0; tp < TT; tp++) acct[tp] = 0.f;
#pragma unroll
    for (int tp = 0; tp < TT; tp++) {
        if (tp <= t) {
            const float* ch = chist + (size_t)tp * BDSZ + (size_t)b * DD;
            acct[tp] = aw[0] * ch[tid] + aw[1] * ch[tid + 128]
                     + aw[2] * ch[tid + 256] + aw[3] * ch[tid + 384];
        }
    }
    __shared__ float wred2[4][TT];
#pragma unroll
    for (int tp = 0; tp < TT; tp++) {
        float x = acct[tp];
        for (int off = 16; off; off >>= 1) x += __shfl_down_sync(~0u, x, off);
        if (lane == 0) wred2[warp][tp] = x;
    }
    __syncthreads();
    __shared__ float sattn[TT];
    if (tid == 0) {
        int nt = t + 1;
        float slog[TT];
        float mx = -1e30f;
        for (int tp = 0; tp < nt; tp++) {
            float vv = wred2[0][tp] + wred2[1][tp] + wred2[2][tp] + wred2[3][tp];
            slog[tp] = vv;
            mx = fmaxf(mx, vv);
        }
        float tot = 0.f;
        for (int tp = 0; tp < nt; tp++) { float ee = expf(slog[tp] - mx); slog[tp] = ee; tot += ee; }
        for (int tp = 0; tp < nt; tp++) sattn[tp] = slog[tp] / tot;
        for (int tp = nt; tp < TT; tp++) sattn[tp] = 0.f;
    }
    __syncthreads();
#pragma unroll
    for (int i = 0; i < 4; i++) {
        int d = tid + i * 128;
        float sv = 0.f;
#pragma unroll
        for (int tp = 0; tp < TT; tp++)
            if (tp <= t) sv += sattn[tp] * mhist[(size_t)tp * BDSZ + (size_t)b * DD + d];
        msa[(size_t)b * DD + d] = sv;
    }
}

// ---------------- read attention (sums z partials + u2 inline) ----------------
__global__ void __launch_bounds__(512)
read_attn_k(const float* __restrict__ KBp, const float* __restrict__ pz,
            const float* __restrict__ U, float* __restrict__ mnew)
{
    int b = blockIdx.x, tid = threadIdx.x;
    __shared__ float zs[DD];
    __shared__ float att[HW];
    __shared__ float red[16];
    {
        size_t j = (size_t)b * DD + tid;
        float zv = U[(size_t)b * 2 * DD + DD + tid];  // u2
#pragma unroll
        for (int c = 0; c < 8; c++) zv += pz[(size_t)c * BDSZ + j];
        zs[tid] = zv;
    }
    __syncthreads();
    int warp = tid >> 5, lane = tid & 31;
    const float* base = KBp + (size_t)b * HW * DD;
    for (int hw = warp; hw < HW; hw += 16) {
        const float4* row = (const float4*)(base + (size_t)hw * DD);
        const float4* z4p = (const float4*)zs;
        float acc = 0.f;
#pragma unroll
        for (int i = 0; i < 4; i++) {
            float4 kv = row[lane + i * 32];
            float4 zv = z4p[lane + i * 32];
            acc += kv.x * zv.x + kv.y * zv.y + kv.z * zv.z + kv.w * zv.w;
        }
        for (int off = 16; off; off >>= 1) acc += __shfl_down_sync(~0u, acc, off);
        if (lane == 0) att[hw] = acc;
    }
    __syncthreads();
    float val = (tid < HW) ? att[tid] : -1e30f;
    float m = val;
    for (int off = 16; off; off >>= 1) m = fmaxf(m, __shfl_xor_sync(~0u, m, off));
    if (lane == 0) red[warp] = m;
    __syncthreads();
    if (warp == 0) {
        float mm = (lane < 16) ? red[lane] : -1e30f;
        for (int off = 8; off; off >>= 1) mm = fmaxf(mm, __shfl_xor_sync(~0u, mm, off));
        if (lane == 0) red[0] = mm;
    }
    __syncthreads();
    float mx = red[0];
    float e = (tid < HW) ? expf(val - mx) : 0.f;
    float s = e;
    for (int off = 16; off; off >>= 1) s += __shfl_xor_sync(~0u, s, off);
    __syncthreads();
    if (lane == 0) red[warp] = s;
    __syncthreads();
    if (warp == 0) {
        float ss = (lane < 16) ? red[lane] : 0.f;
        for (int off = 8; off; off >>= 1) ss += __shfl_xor_sync(~0u, ss, off);
        if (lane == 0) red[0] = ss;
    }
    __syncthreads();
    float inv = 1.f / red[0];
    if (tid < HW) att[tid] = e * inv;
    __syncthreads();
    const float* col = base + tid;
    float acc = 0.f;
#pragma unroll 4
    for (int hw = 0; hw < HW; hw++) acc += att[hw] * col[(size_t)hw * DD];
    mnew[(size_t)b * DD + tid] = acc;
}

// ---------------- bcomb = bwm @ Wam_bot + bam ----------------
__global__ void bcomb_k(const float* __restrict__ Wam, const float* __restrict__ bwm,
                        const float* __restrict__ bam, float* __restrict__ bcomb)
{
    int n = blockIdx.x * 128 + threadIdx.x;
    float s = bam[n];
#pragma unroll 8
    for (int j = 0; j < DD; j++) s += bwm[j] * Wam[(size_t)(DD + j) * DD + n];
    bcomb[n] = s;
}

// ---------------- host helpers ----------------
static GP mkp(const float* A0, int lda0, int K, const float* W, int wtrans, int ldw,
              float* part, int M, int N, int KC)
{
    GP p;
    p.A0 = A0; p.A1 = nullptr; p.A2 = nullptr;
    p.lda0 = lda0; p.lda1 = 0; p.lda2 = 0;
    p.K0 = K; p.K01 = K; p.K = K;
    p.W = W; p.wtrans = wtrans; p.ldw = ldw;
    p.part = part; p.M = M; p.N = N; p.KC = KC;
    return p;
}
static void runp1(const GP& a)
{
    dim3 g((a.N >> 5) * (a.M >> 7), a.K / a.KC, 1);
    gpartial_k<<<g, 256>>>(a, a);
}
static void runp2(const GP& a, const GP& b)
{
    int gx = (a.N >> 5) * (a.M >> 7);
    int gx2 = (b.N >> 5) * (b.M >> 7);
    if (gx2 > gx) gx = gx2;
    int gy = a.K / a.KC, gy2 = b.K / b.KC;
    if (gy2 > gy) gy = gy2;
    dim3 g(gx, gy, 2);
    gpartial_k<<<g, 256>>>(a, b);
}

extern "C" void kernel_launch(void* const* d_in, const int* in_sizes, int n_in,
                              void* d_out, int out_size)
{
    const float* q   = (const float*)d_in[0];
    const float* cws = (const float*)d_in[1];
    const float* KB  = (const float*)d_in[2];
    const float* c0  = (const float*)d_in[3];
    const float* m0  = (const float*)d_in[4];
    const float* Wq  = (const float*)d_in[5];
    const float* bq  = (const float*)d_in[6];
    const float* Wct = (const float*)d_in[7];
    const float* bct = (const float*)d_in[8];
    const float* wca = (const float*)d_in[9];
    const float* Wm  = (const float*)d_in[11];
    const float* bm  = (const float*)d_in[12];
    const float* Wkb = (const float*)d_in[13];
    const float* Wrm = (const float*)d_in[15];
    const float* wra = (const float*)d_in[17];
    const float* Wwm = (const float*)d_in[19];
    const float* bwm = (const float*)d_in[20];
    const float* wwa = (const float*)d_in[21];
    const float* Wam = (const float*)d_in[23];
    const float* bam = (const float*)d_in[24];
    const float* Wg  = (const float*)d_in[25];
    const float* bg  = (const float*)d_in[26];

    float *KBp, *chist, *mhist, *qi, *cq0, *v, *U, *mnew, *msa, *Wcomb, *bcomb;
    float *p_cq, *p_mp, *p_U, *p_g, *p_z, *p_f, *p_set;
    cudaGetSymbolAddress((void**)&KBp,   g_KBp);
    cudaGetSymbolAddress((void**)&chist, g_chist);
    cudaGetSymbolAddress((void**)&mhist, g_mhist);
    cudaGetSymbolAddress((void**)&qi,    g_qi);
    cudaGetSymbolAddress((void**)&cq0,   g_cq0);
    cudaGetSymbolAddress((void**)&v,     g_v);
    cudaGetSymbolAddress((void**)&U,     g_U);
    cudaGetSymbolAddress((void**)&mnew,  g_mnew);
    cudaGetSymbolAddress((void**)&msa,   g_msa);
    cudaGetSymbolAddress((void**)&Wcomb, g_Wcomb);
    cudaGetSymbolAddress((void**)&bcomb, g_bcomb);
    cudaGetSymbolAddress((void**)&p_cq,  g_p_cq);
    cudaGetSymbolAddress((void**)&p_mp,  g_p_mp);
    cudaGetSymbolAddress((void**)&p_U,   g_p_U);
    cudaGetSymbolAddress((void**)&p_g,   g_p_g);
    cudaGetSymbolAddress((void**)&p_z,   g_p_z);
    cudaGetSymbolAddress((void**)&p_f,   g_p_f);
    cudaGetSymbolAddress((void**)&p_set, g_p_set);

    // ---- setup ----
    cudaMemcpyAsync(chist, c0, BDSZ * sizeof(float), cudaMemcpyDeviceToDevice);
    cudaMemcpyAsync(mhist, m0, BDSZ * sizeof(float), cudaMemcpyDeviceToDevice);
    cudaMemcpyAsync(Wcomb, Wam, (size_t)DD * DD * sizeof(float), cudaMemcpyDeviceToDevice);

    transpose_kb_k<<<dim3((HW + 31) / 32, DD / 32, BB), dim3(32, 8)>>>(KB, KBp);
    bcomb_k<<<4, 128>>>(Wam, bwm, bam, bcomb);

    // qi = q @ Wq + bq
    runp1(mkp(q, DD, DD, Wq, 0, DD, p_set, BB, DD, 128));
    reduce0_k<<<BDSZ / 256, 256>>>(p_set, 4, BDSZ, DD, bq, qi);
    // cq0 = qi @ Wct_top + bct
    runp1(mkp(qi, DD, DD, Wct, 0, DD, p_set, BB, DD, 128));
    reduce0_k<<<BDSZ / 256, 256>>>(p_set, 4, BDSZ, DD, bct, cq0);
    // Wcomb rows 512..1535 = Wwm @ Wam_bot   (M = 1024)
    runp1(mkp(Wwm, DD, DD, Wam + (size_t)DD * DD, 0, DD, p_set, 2 * DD, DD, 128));
    reduce0_k<<<(2 * DD * DD) / 256, 256>>>(p_set, 4, 2 * DD * DD, DD, nullptr,
                                            Wcomb + (size_t)DD * DD);

    for (int t = 0; t < TT; t++) {
        const float* chist_t  = chist + (size_t)t * BDSZ;
        const float* mhist_t  = mhist + (size_t)t * BDSZ;
        float*       mhist_t1 = mhist + (size_t)(t + 1) * BDSZ;
        const float* ci_cur   = chist + (size_t)(t + 1) * BDSZ;

        // 1) partials: cq_bot (c_prev @ Wct_bot)  ||  mp (m_prev @ Wm)
        runp2(mkp(chist_t, DD, DD, Wct + (size_t)DD * DD, 0, DD, p_cq, BB, DD, 128),
              mkp(mhist_t, DD, DD, Wm, 0, DD, p_mp, BB, DD, 128));
        // 2) merged control + self attention (sums cq partials, adds cq0)
        attn1_k<<<BB, 128>>>(p_cq, cq0, cws, wca, wra, wwa, chist, mhist, t, v, msa);
        // 3) partials: U (v @ Wrm^T)  ||  g-pre (c_i @ Wg)
        runp2(mkp(v, DD, DD, Wrm, 1, DD, p_U, BB, 2 * DD, 128),
              mkp(ci_cur, DD, DD, Wg, 0, DD, p_g, BB, DD, 128));
        // 4) reduce U with mp epilogue
        reduceU_k<<<(BB * 2 * DD) / 256, 256>>>(p_U, p_mp, bm, U);
        // 5) partials: z = y @ Wkb^T   (y = U cols 0..511, lda = 1024)
        runp1(mkp(U, 2 * DD, DD, Wkb, 1, DD, p_z, BB, DD, 64));
        // 6) read attention (sums z partials + u2)
        read_attn_k<<<BB, 512>>>(KBp, p_z, U, mnew);
        // 7) partials: final = [m_sa | m_new | m_prev] @ Wcomb  (K = 1536)
        {
            GP p = mkp(msa, DD, 3 * DD, Wcomb, 0, DD, p_f, BB, DD, 128);
            p.A1 = mnew;    p.lda1 = DD;
            p.A2 = mhist_t; p.lda2 = DD;
            p.K0 = DD; p.K01 = 2 * DD;
            runp1(p);
        }
        // 8) reduce final + sigmoid gate -> mhist[t+1]
        reduceF_k<<<BDSZ / 256, 256>>>(p_f, p_g, bg, bcomb, mhist_t, mhist_t1);
    }

    cudaMemcpyAsync(d_out, mhist + (size_t)TT * BDSZ, BDSZ * sizeof(float),
                    cudaMemcpyDeviceToDevice);
}